// round 13
// baseline (speedup 1.0000x reference)
#include <cuda_runtime.h>
#include <cuda_fp16.h>
#include <cstdint>

#define NB 128
#define NT 3
#define NBT (NB*NT)

// ---------------- scratch (zero-init at load; padding never written) -------
__device__ __align__(16) __half g_a1f[NBT * 832 * 64];    // padded 26x32, ch-last
__device__ __align__(16) __half g_a2f[NBT * 224 * 128];   // padded 14x16, ch-last
__device__ __align__(16) __half g_a3h[NB * 110592];
__device__ __align__(16) __half g_a3l[NB * 110592];
__device__ __align__(16) __half g_fwh[100 * 110592];
__device__ __align__(16) __half g_fwl[100 * 110592];
__device__ float g_wsq2[NT * 128];
__device__ float g_wsq3[NT * 256];
__device__ __align__(16) __half g_w2f[27 * 8192];
__device__ __align__(16) __half g_w3f[54 * 16384];

#define FC_SLABS 216
#define FC_SLAB_K 512
__device__ float g_part[FC_SLABS * NB * 100];

// ---------------- helpers ----------------
static __device__ __forceinline__ uint32_t smem_u32(const void* p) {
    uint32_t a;
    asm("{ .reg .u64 t; cvta.to.shared.u64 t, %1; cvt.u32.u64 %0, t; }" : "=r"(a) : "l"(p));
    return a;
}
static __device__ __forceinline__ uint32_t sw128(uint32_t off) {
    return off ^ ((off >> 3) & 0x70);
}
static __device__ __forceinline__ void cp16(uint32_t dst, const void* src) {
    asm volatile("cp.async.cg.shared.global [%0], [%1], 16;" :: "r"(dst), "l"(src) : "memory");
}
#define CP_COMMIT() asm volatile("cp.async.commit_group;" ::: "memory")
#define CP_WAIT0()  asm volatile("cp.async.wait_group 0;" ::: "memory")
static __device__ __forceinline__ void ldsm_x4(uint32_t* r, uint32_t addr) {
    asm volatile("ldmatrix.sync.aligned.m8n8.x4.shared.b16 {%0,%1,%2,%3}, [%4];"
                 : "=r"(r[0]), "=r"(r[1]), "=r"(r[2]), "=r"(r[3]) : "r"(addr));
}
static __device__ __forceinline__ void ldsm_x2(uint32_t* r, uint32_t addr) {
    asm volatile("ldmatrix.sync.aligned.m8n8.x2.shared.b16 {%0,%1}, [%2];"
                 : "=r"(r[0]), "=r"(r[1]) : "r"(addr));
}
static __device__ __forceinline__ void mma16816(float* d, const uint32_t* a, const uint32_t* b) {
    asm volatile("mma.sync.aligned.m16n8k16.row.col.f32.f16.f16.f32 "
                 "{%0,%1,%2,%3}, {%4,%5,%6,%7}, {%8,%9}, {%0,%1,%2,%3};"
                 : "+f"(d[0]), "+f"(d[1]), "+f"(d[2]), "+f"(d[3])
                 : "r"(a[0]), "r"(a[1]), "r"(a[2]), "r"(a[3]), "r"(b[0]), "r"(b[1]));
}

// ---------------- prep: swizzled weight images + fc hi/lo split ----------------
__global__ void k_prep(const float* __restrict__ W2, const float* __restrict__ W3,
                       const float* __restrict__ fcw) {
    int e = blockIdx.x * blockDim.x + threadIdx.x;
    if (e < 221184) {                         // t, tap, oc(128), k(64)
        int k = e & 63, oc = (e >> 6) & 127;
        int tap = (e >> 13) % 9, t = e / (9 * 8192);
        float w = W2[(t * 128 + oc) * 576 + k * 9 + tap];
        uint32_t sw = sw128((uint32_t)(oc * 128 + k * 2));
        *(__half*)((char*)(g_w2f + (size_t)(t * 9 + tap) * 8192) + sw) = __float2half(w);
    } else if (e < 1105920) {                 // t, half, tap, oc(128), k(128)
        int e2 = e - 221184;
        int k = e2 & 127, oc = (e2 >> 7) & 127;
        int tap = (e2 >> 14) % 9, th = e2 / (9 * 16384);
        int t = th >> 1, half = th & 1;
        float w = W3[(t * 256 + half * 128 + oc) * 1152 + k * 9 + tap];
        uint32_t off = (uint32_t)((k >> 6) * 16384) + sw128((uint32_t)(oc * 128 + (k & 63) * 2));
        *(__half*)((char*)(g_w3f + (size_t)(th * 9 + tap) * 16384) + off) = __float2half(w);
    } else if (e < 1105920 + 2764800) {       // fc weight hi/lo split (4/thread)
        int e2 = e - 1105920;
        float4 w = ((const float4*)fcw)[e2];
        __half h0 = __float2half(w.x), h1 = __float2half(w.y);
        __half h2 = __float2half(w.z), h3 = __float2half(w.w);
        __half l0 = __float2half(w.x - __half2float(h0));
        __half l1 = __float2half(w.y - __half2float(h1));
        __half l2 = __float2half(w.z - __half2float(h2));
        __half l3 = __float2half(w.w - __half2float(h3));
        ((__half2*)g_fwh)[e2 * 2]     = __halves2half2(h0, h1);
        ((__half2*)g_fwh)[e2 * 2 + 1] = __halves2half2(h2, h3);
        ((__half2*)g_fwl)[e2 * 2]     = __halves2half2(l0, l1);
        ((__half2*)g_fwl)[e2 * 2 + 1] = __halves2half2(l2, l3);
    }
}

// wsq: one warp per output channel, shfl reduce
__global__ void __launch_bounds__(256) k_wsq(const float* __restrict__ W2,
                                             const float* __restrict__ W3) {
    int oid = blockIdx.x * 8 + (threadIdx.x >> 5);
    int lane = threadIdx.x & 31;
    float s = 0.f;
    if (oid < NT * 128) {
        const float* p = W2 + oid * 576;
        for (int k = lane; k < 576; k += 32) {
            float w = __half2float(__float2half(p[k])); s += w * w;
        }
    } else {
        const float* p = W3 + (oid - NT * 128) * 1152;
        for (int k = lane; k < 1152; k += 32) {
            float w = __half2float(__float2half(p[k])); s += w * w;
        }
    }
    #pragma unroll
    for (int d = 16; d > 0; d >>= 1) s += __shfl_xor_sync(0xffffffffu, s, d);
    if (lane == 0) {
        if (oid < NT * 128) g_wsq2[oid] = s;
        else g_wsq3[oid - NT * 128] = s;
    }
}

// ---------------- layer 1: fp32 SIMT, y-split, 16 conv outputs/iter ----------
__global__ void __launch_bounds__(256) k_layer1(
    const float* __restrict__ x, const float* __restrict__ W1,
    const float* __restrict__ tri_w, const float* __restrict__ crelu_b,
    const float* __restrict__ sfm_alpha)
{
    __shared__ __align__(16) float xpadL[28 * 52];
    __shared__ float hsq[28 * 48];
    __shared__ float xsqL[24 * 48];
    __shared__ float w1s[64 * 25];
    __shared__ float wsq1s[64];

    const int bt = blockIdx.x, t = bt % NT, h = blockIdx.y, tid = threadIdx.x;

    for (int idx = tid; idx < 28 * 52; idx += 256) {
        int r = idx / 52, c = idx % 52;
        int gr = h * 24 + r - 2, gc = c - 2;
        xpadL[idx] = (gr >= 0 && gr < 48 && gc >= 0 && gc < 48)
                   ? x[bt * 2304 + gr * 48 + gc] : 0.f;
    }
    for (int idx = tid; idx < 1600; idx += 256) w1s[idx] = W1[t * 1600 + idx];
    __syncthreads();

    if (tid < 64) {
        float s = 0.f;
        #pragma unroll
        for (int k = 0; k < 25; ++k) { float w = w1s[tid * 25 + k]; s += w * w; }
        wsq1s[tid] = s;
    }
    // separable window-5 sum of squares: horizontal pass
    for (int idx = tid; idx < 28 * 48; idx += 256) {
        int r = idx / 48, xx = idx % 48;
        const float* row = &xpadL[r * 52 + xx];
        float s = row[0] * row[0];
        #pragma unroll
        for (int k = 1; k < 5; ++k) s += row[k] * row[k];
        hsq[idx] = s;
    }
    __syncthreads();
    // vertical pass
    for (int idx = tid; idx < 24 * 48; idx += 256) {
        xsqL[idx] = hsq[idx] + hsq[idx + 48] + hsq[idx + 96]
                  + hsq[idx + 144] + hsq[idx + 192];
    }
    __syncthreads();

    const int o = tid >> 2, sub = tid & 3;
    float wr[25];
    #pragma unroll
    for (int k = 0; k < 25; ++k) wr[k] = w1s[o * 25 + k];
    const float wq = wsq1s[o];
    const float tw = tri_w[t * 3 + 0], inv_tw = 1.f / tw;
    const float cb = crelu_b[t * 3 + 0];
    const float al = sfm_alpha[t * 2 + 0];
    const float c00 = al * al * al * 0.25f, c01 = al * al * 0.25f;
    const float c10 = al * 0.25f, c11 = 0.25f;

    for (int it = 0; it < 18; ++it) {
        int q = it * 4 + sub;                  // 72 quads: 12 rows x 6 col-groups
        int pi = q / 6, pj8 = (q % 6) * 8;     // conv rows 2*pi..2*pi+1, cols pj8..pj8+7
        float pt[6][12];
        #pragma unroll
        for (int r = 0; r < 6; ++r) {
            const float* row = &xpadL[(2 * pi + r) * 52 + pj8];
            #pragma unroll
            for (int s2 = 0; s2 < 6; ++s2) {
                float2 u = *(const float2*)(row + 2 * s2);
                pt[r][2 * s2] = u.x; pt[r][2 * s2 + 1] = u.y;
            }
        }
        float vv[2][8];
        #pragma unroll
        for (int a = 0; a < 2; ++a)
            #pragma unroll
            for (int b2 = 0; b2 < 8; ++b2) {
                float cr = 0.f;
                #pragma unroll
                for (int ky = 0; ky < 5; ++ky)
                    #pragma unroll
                    for (int kx = 0; kx < 5; ++kx)
                        cr += wr[ky * 5 + kx] * pt[a + ky][b2 + kx];
                float d = xsqL[(2 * pi + a) * 48 + pj8 + b2] - 2.f * cr + wq;
                d = fmaxf(d, 0.f);
                float v = 1.f - fminf(d, tw) * inv_tw;
                vv[a][b2] = (v >= cb) ? v : 0.f;
            }
        int gi = h * 12 + pi;
        size_t cellBase = ((size_t)bt * 832 + (gi + 1) * 32 + (pj8 / 2 + 1)) * 64 + o;
        #pragma unroll
        for (int pp = 0; pp < 4; ++pp) {
            float pool = c00 * vv[0][2 * pp] + c01 * vv[0][2 * pp + 1]
                       + c10 * vv[1][2 * pp] + c11 * vv[1][2 * pp + 1];
            g_a1f[cellBase + (size_t)pp * 64] = __float2half(pool);
        }
    }
}

// ---------------- conv2: implicit GEMM, 256thr/M=96 blocks (3/SM) -----------
#define C2_AB 24576
#define C2_DYN 57344

__global__ void __launch_bounds__(256) k_conv2(
    const float* __restrict__ tri_w, const float* __restrict__ crelu_b,
    const float* __restrict__ sfm_alpha)
{
    extern __shared__ __align__(1024) unsigned char sm[];
    __shared__ uint32_t lutS[96];
    __shared__ float xsqS[96];
    __shared__ float wsqS[128];
    __shared__ float cellsq[192];

    const int bt = blockIdx.x, t = bt % NT, ytile = blockIdx.y;
    const int y0 = ytile * 4;                 // 4 conv rows per block
    const int tid = threadIdx.x, wid = tid >> 5, lane = tid & 31;
    const uint32_t aBase = smem_u32(sm);
    const uint32_t wBase = aBase + C2_AB;

    {   // stage A: padded rows y0..y0+5 (192 cells)
        const uint4* src = (const uint4*)(g_a1f + ((size_t)bt * 832 + y0 * 32) * 64);
        #pragma unroll
        for (int u = 0; u < 6; ++u) {
            int idx = tid + u * 256;
            uint32_t off = sw128((uint32_t)((idx >> 3) * 128 + (idx & 7) * 16));
            *(uint4*)(sm + off) = src[idx];
        }
    }
    {   // stage W tap 0 into buf 0
        const uint4* wsrc = (const uint4*)(g_w2f + (size_t)(t * 9) * 8192);
        uint4* wdst = (uint4*)(sm + C2_AB);
        #pragma unroll
        for (int u = 0; u < 4; ++u) wdst[tid + u * 256] = wsrc[tid + u * 256];
    }
    if (tid < 96) {
        int r = tid / 24, c = tid % 24;
        lutS[tid] = (uint32_t)((r * 32 + c) * 128);
    }
    if (tid < 128) wsqS[tid] = g_wsq2[t * 128 + tid];
    __syncthreads();

    // fused xsq: per-cell channel sumsq (swizzle-invariant row sum)
    if (tid < 192) {
        float s = 0.f;
        #pragma unroll
        for (int ch = 0; ch < 8; ++ch) {
            uint4 v = *(const uint4*)(sm + sw128((uint32_t)(tid * 128 + ch * 16)));
            const __half2* hh = (const __half2*)&v;
            #pragma unroll
            for (int q = 0; q < 4; ++q) {
                float2 f = __half22float2(hh[q]);
                s += f.x * f.x + f.y * f.y;
            }
        }
        cellsq[tid] = s;
    }
    uint32_t lutv[3];
    const int wm = wid >> 2, wn = wid & 3;    // wm 0..1, wn 0..3
    const int pBase = wm * 48, nBase = wn * 32;
    #pragma unroll
    for (int mt = 0; mt < 3; ++mt)
        lutv[mt] = lutS[pBase + mt * 16 + (lane & 7) + ((lane >> 3) & 1) * 8];
    __syncthreads();
    if (tid < 96) {
        int r = tid / 24, c = tid % 24;
        float s = 0.f;
        #pragma unroll
        for (int dr = 0; dr < 3; ++dr)
            #pragma unroll
            for (int dc = 0; dc < 3; ++dc)
                s += cellsq[(r + dr) * 32 + c + dc];
        xsqS[tid] = s;
    }

    const uint32_t aKoff = ((lane >> 4) & 1) * 16;
    const uint32_t bRow4 = (uint32_t)((nBase + ((lane >> 4) & 1) * 8 + (lane & 7)) * 128
                                      + ((lane >> 3) & 1) * 16);

    float acc[3][4][4];
    #pragma unroll
    for (int mt = 0; mt < 3; ++mt)
        #pragma unroll
        for (int nt = 0; nt < 4; ++nt)
            #pragma unroll
            for (int e = 0; e < 4; ++e) acc[mt][nt][e] = 0.f;

    for (int tap = 0; tap < 9; ++tap) {
        if (tap < 8) {   // cp.async prefetch next tap
            const char* wsrc = (const char*)(g_w2f + (size_t)(t * 9 + tap + 1) * 8192);
            uint32_t wdst = wBase + (((tap + 1) & 1) << 14);
            #pragma unroll
            for (int u = 0; u < 4; ++u)
                cp16(wdst + (tid + u * 256) * 16, wsrc + (tid + u * 256) * 16);
            CP_COMMIT();
        }
        const uint32_t wb = wBase + ((tap & 1) << 14);
        const uint32_t tapOff = (uint32_t)(((tap / 3) * 32 + (tap % 3)) * 128);
        #pragma unroll
        for (int ks = 0; ks < 4; ++ks) {
            const uint32_t kb = ks * 32;
            uint32_t a[3][4], b4[2][4];
            #pragma unroll
            for (int mt = 0; mt < 3; ++mt)
                ldsm_x4(a[mt], aBase + sw128(lutv[mt] + tapOff + kb + aKoff));
            ldsm_x4(b4[0], wb + sw128(bRow4 + kb));
            ldsm_x4(b4[1], wb + sw128(bRow4 + kb + 2048));
            #pragma unroll
            for (int mt = 0; mt < 3; ++mt)
                #pragma unroll
                for (int p2 = 0; p2 < 2; ++p2)
                    #pragma unroll
                    for (int q = 0; q < 2; ++q)
                        mma16816(acc[mt][2 * p2 + q], a[mt], b4[p2] + 2 * q);
        }
        if (tap < 8) CP_WAIT0();
        __syncthreads();
    }

    const float tw = tri_w[t * 3 + 1], inv_tw = 1.f / tw;
    const float cb = crelu_b[t * 3 + 1];
    const float al = sfm_alpha[t * 2 + 1];
    const float c00 = al * al * al * 0.25f, c01 = al * al * 0.25f;
    const float c10 = al * 0.25f, c11 = 0.25f;
    float* vbuf = (float*)sm;   // [96][130] = 49920 B

    #pragma unroll
    for (int mt = 0; mt < 3; ++mt)
        #pragma unroll
        for (int nt = 0; nt < 4; ++nt)
            #pragma unroll
            for (int e = 0; e < 4; ++e) {
                int p = pBase + mt * 16 + (lane >> 2) + (e >= 2 ? 8 : 0);
                int oc = nBase + nt * 8 + 2 * (lane & 3) + (e & 1);
                float d = fmaxf(xsqS[p] - 2.f * acc[mt][nt][e] + wsqS[oc], 0.f);
                float v = 1.f - fminf(d, tw) * inv_tw;
                vbuf[p * 130 + oc] = (v >= cb) ? v : 0.f;
            }
    __syncthreads();

    #pragma unroll
    for (int u = 0; u < 12; ++u) {
        int idx = tid + u * 256;
        int oc = idx & 127, q = idx >> 7;       // q: 0..23
        int pr = q / 12, pc = q % 12;
        int p00 = (2 * pr) * 24 + 2 * pc;
        float pooled = c00 * vbuf[p00 * 130 + oc] + c01 * vbuf[(p00 + 1) * 130 + oc]
                     + c10 * vbuf[(p00 + 24) * 130 + oc] + c11 * vbuf[(p00 + 25) * 130 + oc];
        int gi = ytile * 2 + pr;
        g_a2f[((size_t)bt * 224 + (gi + 1) * 16 + (pc + 1)) * 128 + oc] = __float2half(pooled);
    }
}

// ---------------- conv3: implicit GEMM, fused xsq, cp.async W prefetch -------
#define C3_AP 28672
#define C3_WB 57344
#define C3_DYN 90112

__global__ void __launch_bounds__(384) k_conv3(
    const float* __restrict__ tri_w, const float* __restrict__ crelu_b)
{
    extern __shared__ __align__(1024) unsigned char sm[];
    __shared__ uint32_t lutS[144];
    __shared__ float xsqS3[144];
    __shared__ float wsqS[128];
    __shared__ float cellsq3[224];

    const int bt = blockIdx.x, t = bt % NT, b = bt / NT;
    const int half = blockIdx.y;
    const int tid = threadIdx.x, wid = tid >> 5, lane = tid & 31;
    const uint32_t aBase = smem_u32(sm);
    const uint32_t wBase = aBase + C3_WB;
    const uint4* wImg = (const uint4*)g_w3f + (size_t)((t * 2 + half) * 9) * 2048;

    {   // stage A: 224 cells x 256B, 2 k-planes
        const uint4* src = (const uint4*)(g_a2f + (size_t)bt * 224 * 128);
        for (int idx = tid; idx < 3584; idx += 384) {
            int cell = idx >> 4, chunk = idx & 15;
            uint32_t off = (uint32_t)((chunk >> 3) * C3_AP)
                         + sw128((uint32_t)(cell * 128 + (chunk & 7) * 16));
            *(uint4*)(sm + off) = src[idx];
        }
    }
    {   // stage W step 0
        uint4* wdst = (uint4*)(sm + C3_WB);
        for (int i = tid; i < 1024; i += 384) wdst[i] = wImg[i];
    }
    if (tid < 144) {
        int r = tid / 12, c = tid % 12;
        lutS[tid] = (uint32_t)((r * 16 + c) * 128);
    }
    if (tid < 128) wsqS[tid] = g_wsq3[t * 256 + half * 128 + tid];
    __syncthreads();

    // fused xsq3
    if (tid < 224) {
        float s = 0.f;
        #pragma unroll
        for (int pl = 0; pl < 2; ++pl)
            #pragma unroll
            for (int ch = 0; ch < 8; ++ch) {
                uint4 v = *(const uint4*)(sm + pl * C3_AP
                                          + sw128((uint32_t)(tid * 128 + ch * 16)));
                const __half2* hh = (const __half2*)&v;
                #pragma unroll
                for (int q = 0; q < 4; ++q) {
                    float2 f = __half22float2(hh[q]);
                    s += f.x * f.x + f.y * f.y;
                }
            }
        cellsq3[tid] = s;
    }
    uint32_t lutv[3];
    const int wm = wid >> 2, wn = wid & 3;
    const int pBase = wm * 48, nBase = wn * 32;
    #pragma unroll
    for (int mt = 0; mt < 3; ++mt)
        lutv[mt] = lutS[pBase + mt * 16 + (lane & 7) + ((lane >> 3) & 1) * 8];
    __syncthreads();
    if (tid < 144) {
        int r = tid / 12, c = tid % 12;
        float s = 0.f;
        #pragma unroll
        for (int dr = 0; dr < 3; ++dr)
            #pragma unroll
            for (int dc = 0; dc < 3; ++dc)
                s += cellsq3[(r + dr) * 16 + c + dc];
        xsqS3[tid] = s;
    }

    const uint32_t aKoff = ((lane >> 4) & 1) * 16;
    const uint32_t bRow4 = (uint32_t)((nBase + ((lane >> 4) & 1) * 8 + (lane & 7)) * 128
                                      + ((lane >> 3) & 1) * 16);

    float acc[3][4][4];
    #pragma unroll
    for (int mt = 0; mt < 3; ++mt)
        #pragma unroll
        for (int nt = 0; nt < 4; ++nt)
            #pragma unroll
            for (int e = 0; e < 4; ++e) acc[mt][nt][e] = 0.f;

    for (int s = 0; s < 18; ++s) {             // (tap, plane) steps
        if (s < 17) {                          // cp.async prefetch next step
            int s1 = s + 1;
            const char* wsrc = (const char*)(wImg + (s1 >> 1) * 2048 + (s1 & 1) * 1024);
            uint32_t wdst = wBase + ((s1 & 1) << 14);
            for (int i = tid; i < 1024; i += 384)
                cp16(wdst + i * 16, wsrc + i * 16);
            CP_COMMIT();
        }
        const int tap = s >> 1, pl = s & 1;
        const uint32_t aplane = pl ? (uint32_t)C3_AP : 0u;
        const uint32_t wb = wBase + ((s & 1) << 14);
        const uint32_t tapOff = (uint32_t)(((tap / 3) * 16 + (tap % 3)) * 128);
        #pragma unroll
        for (int ks = 0; ks < 4; ++ks) {
            const uint32_t kb = ks * 32;
            uint32_t a[3][4], b4[2][4];
            #pragma unroll
            for (int mt = 0; mt < 3; ++mt)
                ldsm_x4(a[mt], aBase + aplane + sw128(lutv[mt] + tapOff + kb + aKoff));
            ldsm_x4(b4[0], wb + sw128(bRow4 + kb));
            ldsm_x4(b4[1], wb + sw128(bRow4 + kb + 2048));
            #pragma unroll
            for (int mt = 0; mt < 3; ++mt)
                #pragma unroll
                for (int p2 = 0; p2 < 2; ++p2)
                    #pragma unroll
                    for (int q = 0; q < 2; ++q)
                        mma16816(acc[mt][2 * p2 + q], a[mt], b4[p2] + 2 * q);
        }
        if (s < 17) CP_WAIT0();
        __syncthreads();
    }

    // epilogue: hi/lo split via smem, coalesced stores
    const float tw = tri_w[t * 3 + 2], inv_tw = 1.f / tw;
    const float cb = crelu_b[t * 3 + 2];
    __half2* sOut = (__half2*)sm;    // [128][144] half2 = 73728 B

    #pragma unroll
    for (int mt = 0; mt < 3; ++mt)
        #pragma unroll
        for (int nt = 0; nt < 4; ++nt)
            #pragma unroll
            for (int e = 0; e < 4; ++e) {
                int p = pBase + mt * 16 + (lane >> 2) + (e >= 2 ? 8 : 0);
                int oc = nBase + nt * 8 + 2 * (lane & 3) + (e & 1);
                float d = fmaxf(xsqS3[p] - 2.f * acc[mt][nt][e] + wsqS[oc], 0.f);
                float v = 1.f - fminf(d, tw) * inv_tw;
                v = (v >= cb) ? v : 0.f;
                __half hi = __float2half(v);
                __half lo = __float2half(v - __half2float(hi));
                sOut[oc * 144 + p] = __halves2half2(hi, lo);
            }
    __syncthreads();
    size_t base = (size_t)b * 110592 + t * 36864 + half * 18432;
    for (int idx = tid; idx < 18432; idx += 384) {
        __half2 hv = sOut[idx];
        g_a3h[base + idx] = __low2half(hv);
        g_a3l[base + idx] = __high2half(hv);
    }
}

// ---------------- FC: fp16 mma, 3-pass hi/lo, double-buffered cp.async -------
#define FC_AH 0
#define FC_AL 8192
#define FC_WH 16384
#define FC_WL 23040
#define FC_BUF 29696
#define FC_DYN 59392

__global__ void __launch_bounds__(256) k_fc_mma() {
    extern __shared__ __align__(1024) unsigned char smc[];
    const int blk = blockIdx.x, tid = threadIdx.x, wid = tid >> 5, lane = tid & 31;
    const int k0 = blk * FC_SLAB_K;
    const uint32_t smB = smem_u32(smc);

    // zero-init W rows 100..103 (never re-written; cp.async only stages r<100)
    {
        uint4 z = {0u, 0u, 0u, 0u};
        for (int idx = tid; idx < 32; idx += 256) {
            int bsel = idx >> 4, r = 100 + ((idx >> 2) & 3), c = idx & 3;
            uint32_t sw = sw128((uint32_t)(r * 64 + c * 16));
            *(uint4*)(smc + bsel * FC_BUF + FC_WH + sw) = z;
            *(uint4*)(smc + bsel * FC_BUF + FC_WL + sw) = z;
        }
    }

    float acc[13][4];
    #pragma unroll
    for (int nt = 0; nt < 13; ++nt)
        #pragma unroll
        for (int e = 0; e < 4; ++e) acc[nt][e] = 0.f;

    const int mBase = wid * 16;
    const uint32_t aRow = (uint32_t)(mBase + (lane & 7) + ((lane >> 3) & 1) * 8);
    const uint32_t aK16 = ((lane >> 4) & 1) * 16;
    const uint32_t bK16 = ((lane >> 3) & 1) * 16;
    const uint32_t bRowSel = ((lane >> 4) & 1) * 8 + (lane & 7);

    // prologue: stage chunk 0 into buffer 0
    {
        int kb = k0;
        uint32_t base = smB;
        for (int idx = tid; idx < 512; idx += 256) {
            int r = idx >> 2, c = idx & 3;
            uint32_t sw = sw128((uint32_t)(r * 64 + c * 16));
            cp16(base + FC_AH + sw, g_a3h + (size_t)r * 110592 + kb + c * 8);
            cp16(base + FC_AL + sw, g_a3l + (size_t)r * 110592 + kb + c * 8);
        }
        for (int idx = tid; idx < 400; idx += 256) {
            int r = idx >> 2, c = idx & 3;
            uint32_t sw = sw128((uint32_t)(r * 64 + c * 16));
            cp16(base + FC_WH + sw, g_fwh + (size_t)r * 110592 + kb + c * 8);
            cp16(base + FC_WL + sw, g_fwl + (size_t)r * 110592 + kb + c * 8);
        }
        CP_COMMIT();
        CP_WAIT0();
    }
    __syncthreads();

    for (int ch = 0; ch < 16; ++ch) {
        if (ch < 15) {   // prefetch next chunk into other buffer
            int kb = k0 + (ch + 1) * 32;
            uint32_t base = smB + ((ch + 1) & 1) * FC_BUF;
            for (int idx = tid; idx < 512; idx += 256) {
                int r = idx >> 2, c = idx & 3;
                uint32_t sw = sw128((uint32_t)(r * 64 + c * 16));
                cp16(base + FC_AH + sw, g_a3h + (size_t)r * 110592 + kb + c * 8);
                cp16(base + FC_AL + sw, g_a3l + (size_t)r * 110592 + kb + c * 8);
            }
            for (int idx = tid; idx < 400; idx += 256) {
                int r = idx >> 2, c = idx & 3;
                uint32_t sw = sw128((uint32_t)(r * 64 + c * 16));
                cp16(base + FC_WH + sw, g_fwh + (size_t)r * 110592 + kb + c * 8);
                cp16(base + FC_WL + sw, g_fwl + (size_t)r * 110592 + kb + c * 8);
            }
            CP_COMMIT();
        }
        const uint32_t base = smB + (ch & 1) * FC_BUF;
        const uint32_t aH = base + FC_AH, aL = base + FC_AL;
        const uint32_t wH = base + FC_WH, wL = base + FC_WL;

        #pragma unroll
        for (int ks = 0; ks < 2; ++ks) {
            uint32_t ah[4], al[4];
            uint32_t ao = sw128(aRow * 64 + ks * 32 + aK16);
            ldsm_x4(ah, aH + ao);
            ldsm_x4(al, aL + ao);
            #pragma unroll
            for (int np = 0; np < 6; ++np) {
                uint32_t brow = np * 16 + bRowSel;
                uint32_t bo = sw128(brow * 64 + ks * 32 + bK16);
                uint32_t th[4], tl[4];
                ldsm_x4(th, wH + bo);
                ldsm_x4(tl, wL + bo);
                mma16816(acc[2 * np],     ah, th);
                mma16816(acc[2 * np],     ah, tl);
                mma16816(acc[2 * np],     al, th);
                mma16816(acc[2 * np + 1], ah, th + 2);
                mma16816(acc[2 * np + 1], ah, tl + 2);
                mma16816(acc[2 * np + 1], al, th + 2);
            }
            {   // tail rows 96..103 only (x2: lanes 0-15 supply addresses)
                uint32_t brow = 96 + (lane & 7);
                uint32_t bo = sw128(brow * 64 + ks * 32 + bK16);
                uint32_t bh2[2], bl2[2];
                ldsm_x2(bh2, wH + bo);
                ldsm_x2(bl2, wL + bo);
                mma16816(acc[12], ah, bh2);
                mma16816(acc[12], ah, bl2);
                mma16816(acc[12], al, bh2);
            }
        }
        if (ch < 15) CP_WAIT0();
        __syncthreads();
    }

    float* dst = g_part + (size_t)blk * 12800;
    #pragma unroll
    for (int nt = 0; nt < 13; ++nt)
        #pragma unroll
        for (int e = 0; e < 4; ++e) {
            int n = nt * 8 + 2 * (lane & 3) + (e & 1);
            if (n < 100) {
                int m = mBase + (lane >> 2) + (e >= 2 ? 8 : 0);
                dst[m * 100 + n] = acc[nt][e];
            }
        }
}

__global__ void k_fc_reduce(const float* __restrict__ fcb, float* __restrict__ out) {
    int idx = blockIdx.x * blockDim.x + threadIdx.x;
    if (idx >= NB * 100) return;
    int n = idx % 100;
    float s0 = fcb[n], s1 = 0.f, s2 = 0.f, s3 = 0.f;
    #pragma unroll 4
    for (int sb = 0; sb < FC_SLABS; sb += 4) {
        s0 += g_part[(sb + 0) * 12800 + idx];
        s1 += g_part[(sb + 1) * 12800 + idx];
        s2 += g_part[(sb + 2) * 12800 + idx];
        s3 += g_part[(sb + 3) * 12800 + idx];
    }
    out[idx] = (s0 + s1) + (s2 + s3);
}

// ---------------------------------------------------------------------------
extern "C" void kernel_launch(void* const* d_in, const int* in_sizes, int n_in,
                              void* d_out, int out_size) {
    const float* x         = (const float*)d_in[0];
    const float* W1        = (const float*)d_in[1];
    const float* W2        = (const float*)d_in[2];
    const float* W3        = (const float*)d_in[3];
    const float* tri_w     = (const float*)d_in[4];
    const float* crelu_b   = (const float*)d_in[5];
    const float* sfm_alpha = (const float*)d_in[6];
    const float* fcw       = (const float*)d_in[7];
    const float* fcb       = (const float*)d_in[8];
    float* out = (float*)d_out;

    static int attr_done = 0;
    if (!attr_done) {
        cudaFuncSetAttribute(k_conv2, cudaFuncAttributeMaxDynamicSharedMemorySize, C2_DYN);
        cudaFuncSetAttribute(k_conv3, cudaFuncAttributeMaxDynamicSharedMemorySize, C3_DYN);
        cudaFuncSetAttribute(k_fc_mma, cudaFuncAttributeMaxDynamicSharedMemorySize, FC_DYN);
        attr_done = 1;
    }

    k_prep<<<15120, 256>>>(W2, W3, fcw);
    k_wsq<<<144, 256>>>(W2, W3);
    k_layer1<<<dim3(NBT, 2), 256>>>(x, W1, tri_w, crelu_b, sfm_alpha);
    k_conv2<<<dim3(NBT, 6), 256, C2_DYN>>>(tri_w, crelu_b, sfm_alpha);
    k_conv3<<<dim3(NBT, 2), 384, C3_DYN>>>(tri_w, crelu_b);
    k_fc_mma<<<FC_SLABS, 256, FC_DYN>>>();
    k_fc_reduce<<<(NB * 100 + 255) / 256, 256>>>(fcb, out);
}

// round 14
// speedup vs baseline: 1.0575x; 1.0575x over previous
#include <cuda_runtime.h>
#include <cuda_fp16.h>
#include <cstdint>

#define NB 128
#define NT 3
#define NBT (NB*NT)

// ---------------- scratch (zero-init at load; padding never written) -------
__device__ __align__(16) __half g_a1f[NBT * 832 * 64];    // padded 26x32, ch-last
__device__ __align__(16) __half g_a2f[NBT * 224 * 128];   // padded 14x16, ch-last
__device__ __align__(16) __half g_a3h[NB * 110592];
__device__ __align__(16) __half g_a3l[NB * 110592];
__device__ __align__(16) __half g_fwh[100 * 110592];
__device__ __align__(16) __half g_fwl[100 * 110592];
__device__ float g_wsq2[NT * 128];
__device__ float g_wsq3[NT * 256];
__device__ __align__(16) __half g_w2f[27 * 8192];
__device__ __align__(16) __half g_w3f[54 * 16384];

#define FC_SLABS 216
#define FC_SLAB_K 512
__device__ float g_part[FC_SLABS * NB * 100];

// ---------------- helpers ----------------
static __device__ __forceinline__ uint32_t smem_u32(const void* p) {
    uint32_t a;
    asm("{ .reg .u64 t; cvta.to.shared.u64 t, %1; cvt.u32.u64 %0, t; }" : "=r"(a) : "l"(p));
    return a;
}
static __device__ __forceinline__ uint32_t sw128(uint32_t off) {
    return off ^ ((off >> 3) & 0x70);
}
static __device__ __forceinline__ void cp16(uint32_t dst, const void* src) {
    asm volatile("cp.async.cg.shared.global [%0], [%1], 16;" :: "r"(dst), "l"(src) : "memory");
}
#define CP_COMMIT() asm volatile("cp.async.commit_group;" ::: "memory")
#define CP_WAIT0()  asm volatile("cp.async.wait_group 0;" ::: "memory")
static __device__ __forceinline__ void ldsm_x4(uint32_t* r, uint32_t addr) {
    asm volatile("ldmatrix.sync.aligned.m8n8.x4.shared.b16 {%0,%1,%2,%3}, [%4];"
                 : "=r"(r[0]), "=r"(r[1]), "=r"(r[2]), "=r"(r[3]) : "r"(addr));
}
static __device__ __forceinline__ void ldsm_x2(uint32_t* r, uint32_t addr) {
    asm volatile("ldmatrix.sync.aligned.m8n8.x2.shared.b16 {%0,%1}, [%2];"
                 : "=r"(r[0]), "=r"(r[1]) : "r"(addr));
}
static __device__ __forceinline__ void mma16816(float* d, const uint32_t* a, const uint32_t* b) {
    asm volatile("mma.sync.aligned.m16n8k16.row.col.f32.f16.f16.f32 "
                 "{%0,%1,%2,%3}, {%4,%5,%6,%7}, {%8,%9}, {%0,%1,%2,%3};"
                 : "+f"(d[0]), "+f"(d[1]), "+f"(d[2]), "+f"(d[3])
                 : "r"(a[0]), "r"(a[1]), "r"(a[2]), "r"(a[3]), "r"(b[0]), "r"(b[1]));
}

// ---------------- prep: swizzled weight images + fc hi/lo split ----------------
__global__ void k_prep(const float* __restrict__ W2, const float* __restrict__ W3,
                       const float* __restrict__ fcw) {
    int e = blockIdx.x * blockDim.x + threadIdx.x;
    if (e < 221184) {                         // t, tap, oc(128), k(64)
        int k = e & 63, oc = (e >> 6) & 127;
        int tap = (e >> 13) % 9, t = e / (9 * 8192);
        float w = W2[(t * 128 + oc) * 576 + k * 9 + tap];
        uint32_t sw = sw128((uint32_t)(oc * 128 + k * 2));
        *(__half*)((char*)(g_w2f + (size_t)(t * 9 + tap) * 8192) + sw) = __float2half(w);
    } else if (e < 1105920) {                 // t, half, tap, oc(128), k(128)
        int e2 = e - 221184;
        int k = e2 & 127, oc = (e2 >> 7) & 127;
        int tap = (e2 >> 14) % 9, th = e2 / (9 * 16384);
        int t = th >> 1, half = th & 1;
        float w = W3[(t * 256 + half * 128 + oc) * 1152 + k * 9 + tap];
        uint32_t off = (uint32_t)((k >> 6) * 16384) + sw128((uint32_t)(oc * 128 + (k & 63) * 2));
        *(__half*)((char*)(g_w3f + (size_t)(th * 9 + tap) * 16384) + off) = __float2half(w);
    } else if (e < 1105920 + 2764800) {       // fc weight hi/lo split (4/thread)
        int e2 = e - 1105920;
        float4 w = ((const float4*)fcw)[e2];
        __half h0 = __float2half(w.x), h1 = __float2half(w.y);
        __half h2 = __float2half(w.z), h3 = __float2half(w.w);
        __half l0 = __float2half(w.x - __half2float(h0));
        __half l1 = __float2half(w.y - __half2float(h1));
        __half l2 = __float2half(w.z - __half2float(h2));
        __half l3 = __float2half(w.w - __half2float(h3));
        ((__half2*)g_fwh)[e2 * 2]     = __halves2half2(h0, h1);
        ((__half2*)g_fwh)[e2 * 2 + 1] = __halves2half2(h2, h3);
        ((__half2*)g_fwl)[e2 * 2]     = __halves2half2(l0, l1);
        ((__half2*)g_fwl)[e2 * 2 + 1] = __halves2half2(l2, l3);
    }
}

// wsq: one warp per output channel, shfl reduce
__global__ void __launch_bounds__(256) k_wsq(const float* __restrict__ W2,
                                             const float* __restrict__ W3) {
    int oid = blockIdx.x * 8 + (threadIdx.x >> 5);
    int lane = threadIdx.x & 31;
    float s = 0.f;
    if (oid < NT * 128) {
        const float* p = W2 + oid * 576;
        for (int k = lane; k < 576; k += 32) {
            float w = __half2float(__float2half(p[k])); s += w * w;
        }
    } else {
        const float* p = W3 + (oid - NT * 128) * 1152;
        for (int k = lane; k < 1152; k += 32) {
            float w = __half2float(__float2half(p[k])); s += w * w;
        }
    }
    #pragma unroll
    for (int d = 16; d > 0; d >>= 1) s += __shfl_xor_sync(0xffffffffu, s, d);
    if (lane == 0) {
        if (oid < NT * 128) g_wsq2[oid] = s;
        else g_wsq3[oid - NT * 128] = s;
    }
}

// ---------------- layer 1: fp32 SIMT, y-split, 2 pooled outputs/iter ----------
__global__ void __launch_bounds__(256) k_layer1(
    const float* __restrict__ x, const float* __restrict__ W1,
    const float* __restrict__ tri_w, const float* __restrict__ crelu_b,
    const float* __restrict__ sfm_alpha)
{
    __shared__ __align__(16) float xpadL[28 * 52];
    __shared__ float xsqL[24 * 48];
    __shared__ float w1s[64 * 25];
    __shared__ float wsq1s[64];

    const int bt = blockIdx.x, t = bt % NT, h = blockIdx.y, tid = threadIdx.x;

    for (int idx = tid; idx < 28 * 52; idx += 256) {
        int r = idx / 52, c = idx % 52;
        int gr = h * 24 + r - 2, gc = c - 2;
        xpadL[idx] = (gr >= 0 && gr < 48 && gc >= 0 && gc < 48)
                   ? x[bt * 2304 + gr * 48 + gc] : 0.f;
    }
    for (int idx = tid; idx < 1600; idx += 256) w1s[idx] = W1[t * 1600 + idx];
    __syncthreads();

    if (tid < 64) {
        float s = 0.f;
        #pragma unroll
        for (int k = 0; k < 25; ++k) { float w = w1s[tid * 25 + k]; s += w * w; }
        wsq1s[tid] = s;
    }
    for (int idx = tid; idx < 24 * 48; idx += 256) {
        int y = idx / 48, xx = idx % 48;
        float s = 0.f;
        #pragma unroll
        for (int ky = 0; ky < 5; ++ky)
            #pragma unroll
            for (int kx = 0; kx < 5; ++kx) {
                float v = xpadL[(y + ky) * 52 + xx + kx];
                s += v * v;
            }
        xsqL[idx] = s;
    }
    __syncthreads();

    const int o = tid >> 2, sub = tid & 3;
    float wr[25];
    #pragma unroll
    for (int k = 0; k < 25; ++k) wr[k] = w1s[o * 25 + k];
    const float wq = wsq1s[o];
    const float tw = tri_w[t * 3 + 0], inv_tw = 1.f / tw;
    const float cb = crelu_b[t * 3 + 0];
    const float al = sfm_alpha[t * 2 + 0];
    const float c00 = al * al * al * 0.25f, c01 = al * al * 0.25f;
    const float c10 = al * 0.25f, c11 = 0.25f;

    for (int it = 0; it < 36; ++it) {
        int p = it * 4 + sub;
        int pi = p / 12, pj = (p % 12) * 2;
        float pt[6][8];
        #pragma unroll
        for (int r = 0; r < 6; ++r) {
            const float* row = &xpadL[(2 * pi + r) * 52 + 2 * pj];
            #pragma unroll
            for (int s2 = 0; s2 < 4; ++s2) {
                float2 u = *(const float2*)(row + 2 * s2);
                pt[r][2 * s2] = u.x; pt[r][2 * s2 + 1] = u.y;
            }
        }
        float vv[2][4];
        #pragma unroll
        for (int a = 0; a < 2; ++a)
            #pragma unroll
            for (int b2 = 0; b2 < 4; ++b2) {
                float cr = 0.f;
                #pragma unroll
                for (int ky = 0; ky < 5; ++ky)
                    #pragma unroll
                    for (int kx = 0; kx < 5; ++kx)
                        cr += wr[ky * 5 + kx] * pt[a + ky][b2 + kx];
                float d = xsqL[(2 * pi + a) * 48 + 2 * pj + b2] - 2.f * cr + wq;
                d = fmaxf(d, 0.f);
                float v = 1.f - fminf(d, tw) * inv_tw;
                vv[a][b2] = (v >= cb) ? v : 0.f;
            }
        float pool0 = c00 * vv[0][0] + c01 * vv[0][1] + c10 * vv[1][0] + c11 * vv[1][1];
        float pool1 = c00 * vv[0][2] + c01 * vv[0][3] + c10 * vv[1][2] + c11 * vv[1][3];
        int gi = h * 12 + pi;
        size_t cell = ((size_t)bt * 832 + (gi + 1) * 32 + (pj + 1)) * 64 + o;
        g_a1f[cell] = __float2half(pool0);
        g_a1f[cell + 64] = __float2half(pool1);
    }
}

// ---------------- conv2: implicit GEMM, 128thr, 4 warps of 3Mx8N ------------
#define C2_AB 24576
#define C2_DYN 57344

__global__ void __launch_bounds__(128) k_conv2(
    const float* __restrict__ tri_w, const float* __restrict__ crelu_b,
    const float* __restrict__ sfm_alpha)
{
    extern __shared__ __align__(1024) unsigned char sm[];
    __shared__ uint32_t lutS[96];
    __shared__ float xsqS[96];
    __shared__ float wsqS[128];
    __shared__ float cellsq[192];

    const int bt = blockIdx.x, t = bt % NT, ytile = blockIdx.y;
    const int y0 = ytile * 4;                 // 4 conv rows per block
    const int tid = threadIdx.x, wid = tid >> 5, lane = tid & 31;
    const uint32_t aBase = smem_u32(sm);
    const uint32_t wBase = aBase + C2_AB;

    {   // stage A: padded rows y0..y0+5 (192 cells)
        const uint4* src = (const uint4*)(g_a1f + ((size_t)bt * 832 + y0 * 32) * 64);
        #pragma unroll
        for (int u = 0; u < 12; ++u) {
            int idx = tid + u * 128;
            uint32_t off = sw128((uint32_t)((idx >> 3) * 128 + (idx & 7) * 16));
            *(uint4*)(sm + off) = src[idx];
        }
    }
    {   // stage W tap 0 into buf 0
        const uint4* wsrc = (const uint4*)(g_w2f + (size_t)(t * 9) * 8192);
        uint4* wdst = (uint4*)(sm + C2_AB);
        #pragma unroll
        for (int u = 0; u < 8; ++u) wdst[tid + u * 128] = wsrc[tid + u * 128];
    }
    if (tid < 96) {
        int r = tid / 24, c = tid % 24;
        lutS[tid] = (uint32_t)((r * 32 + c) * 128);
    }
    wsqS[tid] = g_wsq2[t * 128 + tid];
    __syncthreads();

    // fused xsq: per-cell channel sumsq (swizzle-invariant row sum)
    for (int ci = tid; ci < 192; ci += 128) {
        float s = 0.f;
        #pragma unroll
        for (int ch = 0; ch < 8; ++ch) {
            uint4 v = *(const uint4*)(sm + sw128((uint32_t)(ci * 128 + ch * 16)));
            const __half2* hh = (const __half2*)&v;
            #pragma unroll
            for (int q = 0; q < 4; ++q) {
                float2 f = __half22float2(hh[q]);
                s += f.x * f.x + f.y * f.y;
            }
        }
        cellsq[ci] = s;
    }
    uint32_t lutv[3];
    const int wm = wid >> 1, wn = wid & 1;    // wm 0..1, wn 0..1
    const int pBase = wm * 48, nBase = wn * 64;
    #pragma unroll
    for (int mt = 0; mt < 3; ++mt)
        lutv[mt] = lutS[pBase + mt * 16 + (lane & 7) + ((lane >> 3) & 1) * 8];
    __syncthreads();
    if (tid < 96) {
        int r = tid / 24, c = tid % 24;
        float s = 0.f;
        #pragma unroll
        for (int dr = 0; dr < 3; ++dr)
            #pragma unroll
            for (int dc = 0; dc < 3; ++dc)
                s += cellsq[(r + dr) * 32 + c + dc];
        xsqS[tid] = s;
    }

    const uint32_t aKoff = ((lane >> 4) & 1) * 16;
    const uint32_t bRow4 = (uint32_t)((nBase + ((lane >> 4) & 1) * 8 + (lane & 7)) * 128
                                      + ((lane >> 3) & 1) * 16);

    float acc[3][8][4];
    #pragma unroll
    for (int mt = 0; mt < 3; ++mt)
        #pragma unroll
        for (int nt = 0; nt < 8; ++nt)
            #pragma unroll
            for (int e = 0; e < 4; ++e) acc[mt][nt][e] = 0.f;

    for (int tap = 0; tap < 9; ++tap) {
        if (tap < 8) {   // cp.async prefetch next tap
            const char* wsrc = (const char*)(g_w2f + (size_t)(t * 9 + tap + 1) * 8192);
            uint32_t wdst = wBase + (((tap + 1) & 1) << 14);
            #pragma unroll
            for (int u = 0; u < 8; ++u)
                cp16(wdst + (tid + u * 128) * 16, wsrc + (tid + u * 128) * 16);
            CP_COMMIT();
        }
        const uint32_t wb = wBase + ((tap & 1) << 14);
        const uint32_t tapOff = (uint32_t)(((tap / 3) * 32 + (tap % 3)) * 128);
        #pragma unroll
        for (int ks = 0; ks < 4; ++ks) {
            const uint32_t kb = ks * 32;
            uint32_t a[3][4], b4[4][4];
            #pragma unroll
            for (int mt = 0; mt < 3; ++mt)
                ldsm_x4(a[mt], aBase + sw128(lutv[mt] + tapOff + kb + aKoff));
            #pragma unroll
            for (int nb = 0; nb < 4; ++nb)
                ldsm_x4(b4[nb], wb + sw128(bRow4 + kb + nb * 2048));
            #pragma unroll
            for (int mt = 0; mt < 3; ++mt)
                #pragma unroll
                for (int nb = 0; nb < 4; ++nb)
                    #pragma unroll
                    for (int q = 0; q < 2; ++q)
                        mma16816(acc[mt][2 * nb + q], a[mt], b4[nb] + 2 * q);
        }
        if (tap < 8) CP_WAIT0();
        __syncthreads();
    }

    const float tw = tri_w[t * 3 + 1], inv_tw = 1.f / tw;
    const float cb = crelu_b[t * 3 + 1];
    const float al = sfm_alpha[t * 2 + 1];
    const float c00 = al * al * al * 0.25f, c01 = al * al * 0.25f;
    const float c10 = al * 0.25f, c11 = 0.25f;
    float* vbuf = (float*)sm;   // [96][130] = 49920 B

    #pragma unroll
    for (int mt = 0; mt < 3; ++mt)
        #pragma unroll
        for (int nt = 0; nt < 8; ++nt)
            #pragma unroll
            for (int e = 0; e < 4; ++e) {
                int p = pBase + mt * 16 + (lane >> 2) + (e >= 2 ? 8 : 0);
                int oc = nBase + nt * 8 + 2 * (lane & 3) + (e & 1);
                float d = fmaxf(xsqS[p] - 2.f * acc[mt][nt][e] + wsqS[oc], 0.f);
                float v = 1.f - fminf(d, tw) * inv_tw;
                vbuf[p * 130 + oc] = (v >= cb) ? v : 0.f;
            }
    __syncthreads();

    #pragma unroll
    for (int u = 0; u < 24; ++u) {
        int idx = tid + u * 128;
        int oc = idx & 127, q = idx >> 7;       // q: 0..23
        int pr = q / 12, pc = q % 12;
        int p00 = (2 * pr) * 24 + 2 * pc;
        float pooled = c00 * vbuf[p00 * 130 + oc] + c01 * vbuf[(p00 + 1) * 130 + oc]
                     + c10 * vbuf[(p00 + 24) * 130 + oc] + c11 * vbuf[(p00 + 25) * 130 + oc];
        int gi = ytile * 2 + pr;
        g_a2f[((size_t)bt * 224 + (gi + 1) * 16 + (pc + 1)) * 128 + oc] = __float2half(pooled);
    }
}

// ---------------- conv3: implicit GEMM, fused xsq, cp.async W prefetch -------
#define C3_AP 28672
#define C3_WB 57344
#define C3_DYN 90112

__global__ void __launch_bounds__(384) k_conv3(
    const float* __restrict__ tri_w, const float* __restrict__ crelu_b)
{
    extern __shared__ __align__(1024) unsigned char sm[];
    __shared__ uint32_t lutS[144];
    __shared__ float xsqS3[144];
    __shared__ float wsqS[128];
    __shared__ float cellsq3[224];

    const int bt = blockIdx.x, t = bt % NT, b = bt / NT;
    const int half = blockIdx.y;
    const int tid = threadIdx.x, wid = tid >> 5, lane = tid & 31;
    const uint32_t aBase = smem_u32(sm);
    const uint32_t wBase = aBase + C3_WB;
    const uint4* wImg = (const uint4*)g_w3f + (size_t)((t * 2 + half) * 9) * 2048;

    {   // stage A: 224 cells x 256B, 2 k-planes
        const uint4* src = (const uint4*)(g_a2f + (size_t)bt * 224 * 128);
        for (int idx = tid; idx < 3584; idx += 384) {
            int cell = idx >> 4, chunk = idx & 15;
            uint32_t off = (uint32_t)((chunk >> 3) * C3_AP)
                         + sw128((uint32_t)(cell * 128 + (chunk & 7) * 16));
            *(uint4*)(sm + off) = src[idx];
        }
    }
    {   // stage W step 0
        uint4* wdst = (uint4*)(sm + C3_WB);
        for (int i = tid; i < 1024; i += 384) wdst[i] = wImg[i];
    }
    if (tid < 144) {
        int r = tid / 12, c = tid % 12;
        lutS[tid] = (uint32_t)((r * 16 + c) * 128);
    }
    if (tid < 128) wsqS[tid] = g_wsq3[t * 256 + half * 128 + tid];
    __syncthreads();

    // fused xsq3
    if (tid < 224) {
        float s = 0.f;
        #pragma unroll
        for (int pl = 0; pl < 2; ++pl)
            #pragma unroll
            for (int ch = 0; ch < 8; ++ch) {
                uint4 v = *(const uint4*)(sm + pl * C3_AP
                                          + sw128((uint32_t)(tid * 128 + ch * 16)));
                const __half2* hh = (const __half2*)&v;
                #pragma unroll
                for (int q = 0; q < 4; ++q) {
                    float2 f = __half22float2(hh[q]);
                    s += f.x * f.x + f.y * f.y;
                }
            }
        cellsq3[tid] = s;
    }
    uint32_t lutv[3];
    const int wm = wid >> 2, wn = wid & 3;
    const int pBase = wm * 48, nBase = wn * 32;
    #pragma unroll
    for (int mt = 0; mt < 3; ++mt)
        lutv[mt] = lutS[pBase + mt * 16 + (lane & 7) + ((lane >> 3) & 1) * 8];
    __syncthreads();
    if (tid < 144) {
        int r = tid / 12, c = tid % 12;
        float s = 0.f;
        #pragma unroll
        for (int dr = 0; dr < 3; ++dr)
            #pragma unroll
            for (int dc = 0; dc < 3; ++dc)
                s += cellsq3[(r + dr) * 16 + c + dc];
        xsqS3[tid] = s;
    }

    const uint32_t aKoff = ((lane >> 4) & 1) * 16;
    const uint32_t bRow4 = (uint32_t)((nBase + ((lane >> 4) & 1) * 8 + (lane & 7)) * 128
                                      + ((lane >> 3) & 1) * 16);

    float acc[3][4][4];
    #pragma unroll
    for (int mt = 0; mt < 3; ++mt)
        #pragma unroll
        for (int nt = 0; nt < 4; ++nt)
            #pragma unroll
            for (int e = 0; e < 4; ++e) acc[mt][nt][e] = 0.f;

    for (int s = 0; s < 18; ++s) {             // (tap, plane) steps
        if (s < 17) {                          // cp.async prefetch next step
            int s1 = s + 1;
            const char* wsrc = (const char*)(wImg + (s1 >> 1) * 2048 + (s1 & 1) * 1024);
            uint32_t wdst = wBase + ((s1 & 1) << 14);
            for (int i = tid; i < 1024; i += 384)
                cp16(wdst + i * 16, wsrc + i * 16);
            CP_COMMIT();
        }
        const int tap = s >> 1, pl = s & 1;
        const uint32_t aplane = pl ? (uint32_t)C3_AP : 0u;
        const uint32_t wb = wBase + ((s & 1) << 14);
        const uint32_t tapOff = (uint32_t)(((tap / 3) * 16 + (tap % 3)) * 128);
        #pragma unroll
        for (int ks = 0; ks < 4; ++ks) {
            const uint32_t kb = ks * 32;
            uint32_t a[3][4], b4[2][4];
            #pragma unroll
            for (int mt = 0; mt < 3; ++mt)
                ldsm_x4(a[mt], aBase + aplane + sw128(lutv[mt] + tapOff + kb + aKoff));
            ldsm_x4(b4[0], wb + sw128(bRow4 + kb));
            ldsm_x4(b4[1], wb + sw128(bRow4 + kb + 2048));
            #pragma unroll
            for (int mt = 0; mt < 3; ++mt)
                #pragma unroll
                for (int p2 = 0; p2 < 2; ++p2)
                    #pragma unroll
                    for (int q = 0; q < 2; ++q)
                        mma16816(acc[mt][2 * p2 + q], a[mt], b4[p2] + 2 * q);
        }
        if (s < 17) CP_WAIT0();
        __syncthreads();
    }

    // epilogue: hi/lo split via smem, coalesced stores
    const float tw = tri_w[t * 3 + 2], inv_tw = 1.f / tw;
    const float cb = crelu_b[t * 3 + 2];
    __half2* sOut = (__half2*)sm;    // [128][144] half2 = 73728 B

    #pragma unroll
    for (int mt = 0; mt < 3; ++mt)
        #pragma unroll
        for (int nt = 0; nt < 4; ++nt)
            #pragma unroll
            for (int e = 0; e < 4; ++e) {
                int p = pBase + mt * 16 + (lane >> 2) + (e >= 2 ? 8 : 0);
                int oc = nBase + nt * 8 + 2 * (lane & 3) + (e & 1);
                float d = fmaxf(xsqS3[p] - 2.f * acc[mt][nt][e] + wsqS[oc], 0.f);
                float v = 1.f - fminf(d, tw) * inv_tw;
                v = (v >= cb) ? v : 0.f;
                __half hi = __float2half(v);
                __half lo = __float2half(v - __half2float(hi));
                sOut[oc * 144 + p] = __halves2half2(hi, lo);
            }
    __syncthreads();
    size_t base = (size_t)b * 110592 + t * 36864 + half * 18432;
    for (int idx = tid; idx < 18432; idx += 384) {
        __half2 hv = sOut[idx];
        g_a3h[base + idx] = __low2half(hv);
        g_a3l[base + idx] = __high2half(hv);
    }
}

// ---------------- FC: fp16 mma, 3-pass hi/lo, double-buffered cp.async -------
#define FC_AH 0
#define FC_AL 8192
#define FC_WH 16384
#define FC_WL 23040
#define FC_BUF 29696
#define FC_DYN 59392

__global__ void __launch_bounds__(256) k_fc_mma() {
    extern __shared__ __align__(1024) unsigned char smc[];
    const int blk = blockIdx.x, tid = threadIdx.x, wid = tid >> 5, lane = tid & 31;
    const int k0 = blk * FC_SLAB_K;
    const uint32_t smB = smem_u32(smc);

    // zero-init W rows 100..103 (never re-written; cp.async only stages r<100)
    {
        uint4 z = {0u, 0u, 0u, 0u};
        for (int idx = tid; idx < 32; idx += 256) {
            int bsel = idx >> 4, r = 100 + ((idx >> 2) & 3), c = idx & 3;
            uint32_t sw = sw128((uint32_t)(r * 64 + c * 16));
            *(uint4*)(smc + bsel * FC_BUF + FC_WH + sw) = z;
            *(uint4*)(smc + bsel * FC_BUF + FC_WL + sw) = z;
        }
    }

    float acc[13][4];
    #pragma unroll
    for (int nt = 0; nt < 13; ++nt)
        #pragma unroll
        for (int e = 0; e < 4; ++e) acc[nt][e] = 0.f;

    const int mBase = wid * 16;
    const uint32_t aRow = (uint32_t)(mBase + (lane & 7) + ((lane >> 3) & 1) * 8);
    const uint32_t aK16 = ((lane >> 4) & 1) * 16;
    const uint32_t bK16 = ((lane >> 3) & 1) * 16;
    const uint32_t bRowSel = ((lane >> 4) & 1) * 8 + (lane & 7);

    // prologue: stage chunk 0 into buffer 0
    {
        int kb = k0;
        uint32_t base = smB;
        for (int idx = tid; idx < 512; idx += 256) {
            int r = idx >> 2, c = idx & 3;
            uint32_t sw = sw128((uint32_t)(r * 64 + c * 16));
            cp16(base + FC_AH + sw, g_a3h + (size_t)r * 110592 + kb + c * 8);
            cp16(base + FC_AL + sw, g_a3l + (size_t)r * 110592 + kb + c * 8);
        }
        for (int idx = tid; idx < 400; idx += 256) {
            int r = idx >> 2, c = idx & 3;
            uint32_t sw = sw128((uint32_t)(r * 64 + c * 16));
            cp16(base + FC_WH + sw, g_fwh + (size_t)r * 110592 + kb + c * 8);
            cp16(base + FC_WL + sw, g_fwl + (size_t)r * 110592 + kb + c * 8);
        }
        CP_COMMIT();
        CP_WAIT0();
    }
    __syncthreads();

    for (int ch = 0; ch < 16; ++ch) {
        if (ch < 15) {   // prefetch next chunk into other buffer
            int kb = k0 + (ch + 1) * 32;
            uint32_t base = smB + ((ch + 1) & 1) * FC_BUF;
            for (int idx = tid; idx < 512; idx += 256) {
                int r = idx >> 2, c = idx & 3;
                uint32_t sw = sw128((uint32_t)(r * 64 + c * 16));
                cp16(base + FC_AH + sw, g_a3h + (size_t)r * 110592 + kb + c * 8);
                cp16(base + FC_AL + sw, g_a3l + (size_t)r * 110592 + kb + c * 8);
            }
            for (int idx = tid; idx < 400; idx += 256) {
                int r = idx >> 2, c = idx & 3;
                uint32_t sw = sw128((uint32_t)(r * 64 + c * 16));
                cp16(base + FC_WH + sw, g_fwh + (size_t)r * 110592 + kb + c * 8);
                cp16(base + FC_WL + sw, g_fwl + (size_t)r * 110592 + kb + c * 8);
            }
            CP_COMMIT();
        }
        const uint32_t base = smB + (ch & 1) * FC_BUF;
        const uint32_t aH = base + FC_AH, aL = base + FC_AL;
        const uint32_t wH = base + FC_WH, wL = base + FC_WL;

        #pragma unroll
        for (int ks = 0; ks < 2; ++ks) {
            uint32_t ah[4], al[4];
            uint32_t ao = sw128(aRow * 64 + ks * 32 + aK16);
            ldsm_x4(ah, aH + ao);
            ldsm_x4(al, aL + ao);
            #pragma unroll
            for (int np = 0; np < 6; ++np) {
                uint32_t brow = np * 16 + bRowSel;
                uint32_t bo = sw128(brow * 64 + ks * 32 + bK16);
                uint32_t th[4], tl[4];
                ldsm_x4(th, wH + bo);
                ldsm_x4(tl, wL + bo);
                mma16816(acc[2 * np],     ah, th);
                mma16816(acc[2 * np],     ah, tl);
                mma16816(acc[2 * np],     al, th);
                mma16816(acc[2 * np + 1], ah, th + 2);
                mma16816(acc[2 * np + 1], ah, tl + 2);
                mma16816(acc[2 * np + 1], al, th + 2);
            }
            {   // tail rows 96..103 only (x2: lanes 0-15 supply addresses)
                uint32_t brow = 96 + (lane & 7);
                uint32_t bo = sw128(brow * 64 + ks * 32 + bK16);
                uint32_t bh2[2], bl2[2];
                ldsm_x2(bh2, wH + bo);
                ldsm_x2(bl2, wL + bo);
                mma16816(acc[12], ah, bh2);
                mma16816(acc[12], ah, bl2);
                mma16816(acc[12], al, bh2);
            }
        }
        if (ch < 15) CP_WAIT0();
        __syncthreads();
    }

    float* dst = g_part + (size_t)blk * 12800;
    #pragma unroll
    for (int nt = 0; nt < 13; ++nt)
        #pragma unroll
        for (int e = 0; e < 4; ++e) {
            int n = nt * 8 + 2 * (lane & 3) + (e & 1);
            if (n < 100) {
                int m = mBase + (lane >> 2) + (e >= 2 ? 8 : 0);
                dst[m * 100 + n] = acc[nt][e];
            }
        }
}

__global__ void k_fc_reduce(const float* __restrict__ fcb, float* __restrict__ out) {
    int idx = blockIdx.x * blockDim.x + threadIdx.x;
    if (idx >= NB * 100) return;
    int n = idx % 100;
    float s0 = fcb[n], s1 = 0.f, s2 = 0.f, s3 = 0.f;
    #pragma unroll 4
    for (int sb = 0; sb < FC_SLABS; sb += 4) {
        s0 += g_part[(sb + 0) * 12800 + idx];
        s1 += g_part[(sb + 1) * 12800 + idx];
        s2 += g_part[(sb + 2) * 12800 + idx];
        s3 += g_part[(sb + 3) * 12800 + idx];
    }
    out[idx] = (s0 + s1) + (s2 + s3);
}

// ---------------------------------------------------------------------------
extern "C" void kernel_launch(void* const* d_in, const int* in_sizes, int n_in,
                              void* d_out, int out_size) {
    const float* x         = (const float*)d_in[0];
    const float* W1        = (const float*)d_in[1];
    const float* W2        = (const float*)d_in[2];
    const float* W3        = (const float*)d_in[3];
    const float* tri_w     = (const float*)d_in[4];
    const float* crelu_b   = (const float*)d_in[5];
    const float* sfm_alpha = (const float*)d_in[6];
    const float* fcw       = (const float*)d_in[7];
    const float* fcb       = (const float*)d_in[8];
    float* out = (float*)d_out;

    static int attr_done = 0;
    if (!attr_done) {
        cudaFuncSetAttribute(k_conv2, cudaFuncAttributeMaxDynamicSharedMemorySize, C2_DYN);
        cudaFuncSetAttribute(k_conv3, cudaFuncAttributeMaxDynamicSharedMemorySize, C3_DYN);
        cudaFuncSetAttribute(k_fc_mma, cudaFuncAttributeMaxDynamicSharedMemorySize, FC_DYN);
        attr_done = 1;
    }

    k_prep<<<15120, 256>>>(W2, W3, fcw);
    k_wsq<<<144, 256>>>(W2, W3);
    k_layer1<<<dim3(NBT, 2), 256>>>(x, W1, tri_w, crelu_b, sfm_alpha);
    k_conv2<<<dim3(NBT, 6), 128, C2_DYN>>>(tri_w, crelu_b, sfm_alpha);
    k_conv3<<<dim3(NBT, 2), 384, C3_DYN>>>(tri_w, crelu_b);
    k_fc_mma<<<FC_SLABS, 256, FC_DYN>>>();
    k_fc_reduce<<<(NB * 100 + 255) / 256, 256>>>(fcb, out);
}